// round 2
// baseline (speedup 1.0000x reference)
#include <cuda_runtime.h>

#define NN 100000
#define NE 1600000
#define NG 1024
#define DD 128
#define NB_SCAN 391   // ceil(NN/256)
#define NB_INIT 512   // ceil(max(NN, NG*DD)/256) = ceil(131072/256)

// ---------------- scratch (device globals; no allocation allowed) ----------------
__device__ float g_agg[NN * DD];
__device__ float g_h1[NN * DD];
__device__ float g_h2[NN * DD];
__device__ float g_pool[NG * DD];
__device__ float g_WT1[2 * DD * DD];   // [k][n], k<128 -> W1l^T, k>=128 -> W1r^T
__device__ float g_WT2[2 * DD * DD];
__device__ int   g_deg[NN];
__device__ int   g_rowptr[NN + 1];
__device__ int   g_cursor[NN];
__device__ int   g_esrc[NE];
__device__ int   g_bsum[512];
__device__ int   g_boff[512];

// ---------------- init ----------------
__global__ void k_init() {
    int i = blockIdx.x * blockDim.x + threadIdx.x;
    if (i < NN) { g_deg[i] = 0; g_cursor[i] = 0; }
    if (i < NG * DD) g_pool[i] = 0.0f;
}

// transpose weights once: g_WT[k][n]
__global__ void k_transp(const float* __restrict__ W1l, const float* __restrict__ W1r,
                         const float* __restrict__ W2l, const float* __restrict__ W2r) {
    int i = blockIdx.x * blockDim.x + threadIdx.x;   // over 2*128*128
    if (i >= 2 * DD * DD) return;
    int k = i / DD, n = i % DD;
    g_WT1[i] = (k < DD) ? W1l[n * DD + k] : W1r[n * DD + (k - DD)];
    g_WT2[i] = (k < DD) ? W2l[n * DD + k] : W2r[n * DD + (k - DD)];
}

// ---------------- CSR build (edge_index is int32: JAX x64 disabled) ----------------
__global__ void k_deg(const int* __restrict__ dst) {
    int i = blockIdx.x * blockDim.x + threadIdx.x;
    if (i < NE) atomicAdd(&g_deg[dst[i]], 1);
}

__global__ void k_scanA() {
    __shared__ int s[256];
    int b = blockIdx.x, t = threadIdx.x;
    int i = b * 256 + t;
    int v = (i < NN) ? g_deg[i] : 0;
    s[t] = v;
    __syncthreads();
#pragma unroll
    for (int off = 1; off < 256; off <<= 1) {
        int add = (t >= off) ? s[t - off] : 0;
        __syncthreads();
        s[t] += add;
        __syncthreads();
    }
    if (i < NN) g_rowptr[i] = s[t] - v;   // local exclusive
    if (t == 255) g_bsum[b] = s[255];
}

__global__ void k_scanB() {
    __shared__ int s[512];
    int t = threadIdx.x;
    int v = (t < NB_SCAN) ? g_bsum[t] : 0;
    s[t] = v;
    __syncthreads();
#pragma unroll
    for (int off = 1; off < 512; off <<= 1) {
        int add = (t >= off) ? s[t - off] : 0;
        __syncthreads();
        s[t] += add;
        __syncthreads();
    }
    if (t < NB_SCAN) g_boff[t] = s[t] - v;   // exclusive
}

__global__ void k_scanC() {
    int i = blockIdx.x * blockDim.x + threadIdx.x;
    if (i < NN) g_rowptr[i] += g_boff[i >> 8];
    if (i == 0) g_rowptr[NN] = NE;
}

__global__ void k_scatter(const int* __restrict__ src, const int* __restrict__ dst) {
    int i = blockIdx.x * blockDim.x + threadIdx.x;
    if (i >= NE) return;
    int d = dst[i];
    int pos = atomicAdd(&g_cursor[d], 1);
    g_esrc[g_rowptr[d] + pos] = src[i];
}

// ---------------- mean aggregation: warp per destination node ----------------
__global__ void k_agg(const float* __restrict__ in, float* __restrict__ out) {
    int w = (blockIdx.x * blockDim.x + threadIdx.x) >> 5;
    int lane = threadIdx.x & 31;
    if (w >= NN) return;
    int beg = g_rowptr[w], end = g_rowptr[w + 1];
    const float4* in4 = (const float4*)in;
    float ax = 0.f, ay = 0.f, az = 0.f, aw = 0.f;
#pragma unroll 4
    for (int e = beg; e < end; e++) {
        int s = __ldg(&g_esrc[e]);
        float4 v = __ldg(&in4[s * 32 + lane]);
        ax += v.x; ay += v.y; az += v.z; aw += v.w;
    }
    float inv = (end > beg) ? 1.0f / (float)(end - beg) : 0.0f;
    float4 r; r.x = ax * inv; r.y = ay * inv; r.z = az * inv; r.w = aw * inv;
    ((float4*)out)[w * 32 + lane] = r;
}

// ---------------- fused SAGE GEMM: out = relu(Ag@Wl^T + b + Bx@Wr^T) ----------------
// Virtual K=256 ([Ag | Bx] against g_WT). Block: 128 rows x 128 cols, 256 threads, 8x8/thread.
__global__ void __launch_bounds__(256, 2)
k_gemm(const float* __restrict__ Ag, const float* __restrict__ Bx,
       const float* __restrict__ WT, const float* __restrict__ bias,
       float* __restrict__ out) {
    __shared__ float sA[16][132];   // [kk][m], padded
    __shared__ float sW[16][128];   // [kk][n]
    int tid = threadIdx.x;
    int tx = tid & 15, ty = tid >> 4;
    int m0 = blockIdx.x * 128;

    int lm = tid >> 1;               // row this thread loads (0..127)
    int lk = (tid & 1) * 8;          // k-offset within tile
    int wkk = tid >> 5;              // 0..7
    int wn = (tid & 31) * 4;

    bool rowok = (m0 + lm) < NN;

    float4 pa0, pa1, pw0, pw1;

    // prefetch tile kt
    auto LD = [&](int kt) {
        int ks = kt * 16;
        const float* src = (ks < DD) ? Ag : Bx;
        int kb = ks & (DD - 1);
        if (rowok) {
            const float4* p = (const float4*)(src + (size_t)(m0 + lm) * DD + kb + lk);
            pa0 = p[0]; pa1 = p[1];
        } else {
            pa0 = make_float4(0, 0, 0, 0); pa1 = pa0;
        }
        pw0 = *(const float4*)(WT + (ks + wkk) * DD + wn);
        pw1 = *(const float4*)(WT + (ks + wkk + 8) * DD + wn);
    };

    float acc[8][8];
#pragma unroll
    for (int i = 0; i < 8; i++)
#pragma unroll
        for (int j = 0; j < 8; j++) acc[i][j] = 0.f;

    LD(0);
#pragma unroll
    for (int kt = 0; kt < 16; kt++) {
        sA[lk + 0][lm] = pa0.x; sA[lk + 1][lm] = pa0.y;
        sA[lk + 2][lm] = pa0.z; sA[lk + 3][lm] = pa0.w;
        sA[lk + 4][lm] = pa1.x; sA[lk + 5][lm] = pa1.y;
        sA[lk + 6][lm] = pa1.z; sA[lk + 7][lm] = pa1.w;
        *(float4*)&sW[wkk][wn] = pw0;
        *(float4*)&sW[wkk + 8][wn] = pw1;
        __syncthreads();
        if (kt < 15) LD(kt + 1);
#pragma unroll
        for (int kk = 0; kk < 16; kk++) {
            float a[8], w[8];
            *(float4*)(a)     = *(float4*)&sA[kk][ty * 8];
            *(float4*)(a + 4) = *(float4*)&sA[kk][ty * 8 + 4];
            *(float4*)(w)     = *(float4*)&sW[kk][tx * 8];
            *(float4*)(w + 4) = *(float4*)&sW[kk][tx * 8 + 4];
#pragma unroll
            for (int i = 0; i < 8; i++)
#pragma unroll
                for (int j = 0; j < 8; j++) acc[i][j] += a[i] * w[j];
        }
        __syncthreads();
    }

    float b[8];
    *(float4*)(b)     = *(const float4*)(bias + tx * 8);
    *(float4*)(b + 4) = *(const float4*)(bias + tx * 8 + 4);
#pragma unroll
    for (int i = 0; i < 8; i++) {
        int m = m0 + ty * 8 + i;
        if (m < NN) {
            float4 o0, o1;
            o0.x = fmaxf(acc[i][0] + b[0], 0.f);
            o0.y = fmaxf(acc[i][1] + b[1], 0.f);
            o0.z = fmaxf(acc[i][2] + b[2], 0.f);
            o0.w = fmaxf(acc[i][3] + b[3], 0.f);
            o1.x = fmaxf(acc[i][4] + b[4], 0.f);
            o1.y = fmaxf(acc[i][5] + b[5], 0.f);
            o1.z = fmaxf(acc[i][6] + b[6], 0.f);
            o1.w = fmaxf(acc[i][7] + b[7], 0.f);
            *(float4*)(out + (size_t)m * DD + tx * 8)     = o0;
            *(float4*)(out + (size_t)m * DD + tx * 8 + 4) = o1;
        }
    }
}

// ---------------- global add pool (batch is sorted, int32) ----------------
#define NPB 256
__global__ void k_pool(const float* __restrict__ h, const int* __restrict__ batch) {
    int t = threadIdx.x;                 // channel 0..127
    int start = blockIdx.x * NPB;
    int end = start + NPB; if (end > NN) end = NN;
    if (start >= NN) return;
    int cur = batch[start];
    float sum = 0.f;
    for (int i = start; i < end; i++) {
        int b = __ldg(&batch[i]);
        if (b != cur) {
            atomicAdd(&g_pool[cur * DD + t], sum);
            sum = 0.f; cur = b;
        }
        sum += h[(size_t)i * DD + t];
    }
    atomicAdd(&g_pool[cur * DD + t], sum);
}

// ---------------- LayerNorm + final linear: one warp per graph ----------------
__global__ void k_final(const float* __restrict__ ln_g, const float* __restrict__ ln_b,
                        const float* __restrict__ Wlin, const float* __restrict__ blin,
                        float* __restrict__ out) {
    int w = (blockIdx.x * blockDim.x + threadIdx.x) >> 5;
    int lane = threadIdx.x & 31;
    if (w >= NG) return;
    float4 v = ((const float4*)g_pool)[w * 32 + lane];
    float s = v.x + v.y + v.z + v.w;
#pragma unroll
    for (int o = 16; o; o >>= 1) s += __shfl_xor_sync(0xffffffffu, s, o);
    float mean = s * (1.0f / 128.0f);
    float dx = v.x - mean, dy = v.y - mean, dz = v.z - mean, dw = v.w - mean;
    float q = dx * dx + dy * dy + dz * dz + dw * dw;
#pragma unroll
    for (int o = 16; o; o >>= 1) q += __shfl_xor_sync(0xffffffffu, q, o);
    float var = q * (1.0f / 128.0f);
    float r = rsqrtf(var + 1e-5f);
    float4 gg = ((const float4*)ln_g)[lane];
    float4 bb = ((const float4*)ln_b)[lane];
    float n0 = dx * r * gg.x + bb.x;
    float n1 = dy * r * gg.y + bb.y;
    float n2 = dz * r * gg.z + bb.z;
    float n3 = dw * r * gg.w + bb.w;
    float4 w0 = ((const float4*)Wlin)[lane];        // row 0
    float4 w1 = ((const float4*)Wlin)[32 + lane];   // row 1
    float d0 = n0 * w0.x + n1 * w0.y + n2 * w0.z + n3 * w0.w;
    float d1 = n0 * w1.x + n1 * w1.y + n2 * w1.z + n3 * w1.w;
#pragma unroll
    for (int o = 16; o; o >>= 1) {
        d0 += __shfl_xor_sync(0xffffffffu, d0, o);
        d1 += __shfl_xor_sync(0xffffffffu, d1, o);
    }
    if (lane == 0) {
        out[w * 2 + 0] = d0 + blin[0];
        out[w * 2 + 1] = d1 + blin[1];
    }
}

// ---------------- launch ----------------
extern "C" void kernel_launch(void* const* d_in, const int* in_sizes, int n_in,
                              void* d_out, int out_size) {
    const float* x     = (const float*)d_in[0];
    const int*   ei    = (const int*)d_in[1];
    const int*   bat   = (const int*)d_in[2];
    const float* W1l   = (const float*)d_in[3];
    const float* b1l   = (const float*)d_in[4];
    const float* W1r   = (const float*)d_in[5];
    const float* W2l   = (const float*)d_in[6];
    const float* b2l   = (const float*)d_in[7];
    const float* W2r   = (const float*)d_in[8];
    const float* ln_g  = (const float*)d_in[9];
    const float* ln_b  = (const float*)d_in[10];
    const float* Wlin  = (const float*)d_in[11];
    const float* blin  = (const float*)d_in[12];

    const int* src = ei;
    const int* dst = ei + NE;

    float *agg, *h1, *h2, *wt1, *wt2;
    cudaGetSymbolAddress((void**)&agg, g_agg);
    cudaGetSymbolAddress((void**)&h1,  g_h1);
    cudaGetSymbolAddress((void**)&h2,  g_h2);
    cudaGetSymbolAddress((void**)&wt1, g_WT1);
    cudaGetSymbolAddress((void**)&wt2, g_WT2);

    k_init<<<NB_INIT, 256>>>();
    k_transp<<<128, 256>>>(W1l, W1r, W2l, W2r);
    k_deg<<<(NE + 255) / 256, 256>>>(dst);
    k_scanA<<<NB_SCAN, 256>>>();
    k_scanB<<<1, 512>>>();
    k_scanC<<<NB_SCAN + 1, 256>>>();
    k_scatter<<<(NE + 255) / 256, 256>>>(src, dst);

    // layer 1
    k_agg<<<(NN * 32 + 255) / 256, 256>>>(x, agg);
    k_gemm<<<(NN + 127) / 128, 256>>>(agg, x, wt1, b1l, h1);
    // layer 2
    k_agg<<<(NN * 32 + 255) / 256, 256>>>(h1, agg);
    k_gemm<<<(NN + 127) / 128, 256>>>(agg, h1, wt2, b2l, h2);

    // pool + layernorm + linear
    k_pool<<<(NN + NPB - 1) / NPB, 128>>>(h2, bat);
    k_final<<<(NG * 32 + 255) / 256, 256>>>(ln_g, ln_b, Wlin, blin, (float*)d_out);
}

// round 3
// speedup vs baseline: 1.1118x; 1.1118x over previous
#include <cuda_runtime.h>

#define NN 100000
#define NE 1600000
#define NG 1024
#define DD 128
#define NB_SCAN 391   // ceil(NN/256)
#define NB_INIT 512   // ceil(max(NN, NG*DD)/256)

// ---------------- scratch (device globals; no allocation allowed) ----------------
__device__ float g_agg[NN * DD];
__device__ float g_h1[NN * DD];
__device__ float g_h2[NN * DD];
__device__ float g_pool[NG * DD];
__device__ float g_WT1[2 * DD * DD];   // [k][n], k<128 -> W1l^T, k>=128 -> W1r^T
__device__ float g_WT2[2 * DD * DD];
__device__ int   g_deg[NN];
__device__ int   g_rowptr[NN + 1];
__device__ int   g_cursor[NN];
__device__ int   g_esrc[NE];
__device__ int   g_bsum[512];
__device__ int   g_boff[512];

// packed f32x2 helpers (sm_103a FFMA2 path — PTX-only)
#define PACK_F32X2(out, lo, hi) \
    asm("mov.b64 %0, {%1, %2};" : "=l"(out) : "f"(lo), "f"(hi))
#define UNPACK_F32X2(lo, hi, in) \
    asm("mov.b64 {%0, %1}, %2;" : "=f"(lo), "=f"(hi) : "l"(in))
#define FMA_F32X2(d, a, b, c) \
    asm("fma.rn.f32x2 %0, %1, %2, %3;" : "=l"(d) : "l"(a), "l"(b), "l"(c))

// ---------------- init ----------------
__global__ void k_init() {
    int i = blockIdx.x * blockDim.x + threadIdx.x;
    if (i < NN) { g_deg[i] = 0; g_cursor[i] = 0; }
    if (i < NG * DD) g_pool[i] = 0.0f;
}

// transpose weights once: g_WT[k][n]
__global__ void k_transp(const float* __restrict__ W1l, const float* __restrict__ W1r,
                         const float* __restrict__ W2l, const float* __restrict__ W2r) {
    int i = blockIdx.x * blockDim.x + threadIdx.x;   // over 2*128*128
    if (i >= 2 * DD * DD) return;
    int k = i / DD, n = i % DD;
    g_WT1[i] = (k < DD) ? W1l[n * DD + k] : W1r[n * DD + (k - DD)];
    g_WT2[i] = (k < DD) ? W2l[n * DD + k] : W2r[n * DD + (k - DD)];
}

// ---------------- CSR build (edge_index is int32: JAX x64 disabled) ----------------
__global__ void k_deg(const int* __restrict__ dst) {
    int i = blockIdx.x * blockDim.x + threadIdx.x;
    if (i < NE) atomicAdd(&g_deg[dst[i]], 1);
}

__global__ void k_scanA() {
    __shared__ int s[256];
    int b = blockIdx.x, t = threadIdx.x;
    int i = b * 256 + t;
    int v = (i < NN) ? g_deg[i] : 0;
    s[t] = v;
    __syncthreads();
#pragma unroll
    for (int off = 1; off < 256; off <<= 1) {
        int add = (t >= off) ? s[t - off] : 0;
        __syncthreads();
        s[t] += add;
        __syncthreads();
    }
    if (i < NN) g_rowptr[i] = s[t] - v;   // local exclusive
    if (t == 255) g_bsum[b] = s[255];
}

__global__ void k_scanB() {
    __shared__ int s[512];
    int t = threadIdx.x;
    int v = (t < NB_SCAN) ? g_bsum[t] : 0;
    s[t] = v;
    __syncthreads();
#pragma unroll
    for (int off = 1; off < 512; off <<= 1) {
        int add = (t >= off) ? s[t - off] : 0;
        __syncthreads();
        s[t] += add;
        __syncthreads();
    }
    if (t < NB_SCAN) g_boff[t] = s[t] - v;   // exclusive
}

__global__ void k_scanC() {
    int i = blockIdx.x * blockDim.x + threadIdx.x;
    if (i < NN) g_rowptr[i] += g_boff[i >> 8];
    if (i == 0) g_rowptr[NN] = NE;
}

__global__ void k_scatter(const int* __restrict__ src, const int* __restrict__ dst) {
    int i = blockIdx.x * blockDim.x + threadIdx.x;
    if (i >= NE) return;
    int d = dst[i];
    int pos = atomicAdd(&g_cursor[d], 1);
    g_esrc[g_rowptr[d] + pos] = src[i];
}

// ---------------- mean aggregation: warp per destination node ----------------
__global__ void k_agg(const float* __restrict__ in, float* __restrict__ out) {
    int w = (blockIdx.x * blockDim.x + threadIdx.x) >> 5;
    int lane = threadIdx.x & 31;
    if (w >= NN) return;
    int beg = g_rowptr[w], end = g_rowptr[w + 1];
    const float4* in4 = (const float4*)in;
    float ax = 0.f, ay = 0.f, az = 0.f, aw = 0.f;
#pragma unroll 4
    for (int e = beg; e < end; e++) {
        int s = __ldg(&g_esrc[e]);
        float4 v = __ldg(&in4[s * 32 + lane]);
        ax += v.x; ay += v.y; az += v.z; aw += v.w;
    }
    float inv = (end > beg) ? 1.0f / (float)(end - beg) : 0.0f;
    float4 r; r.x = ax * inv; r.y = ay * inv; r.z = az * inv; r.w = aw * inv;
    ((float4*)out)[w * 32 + lane] = r;
}

// ---------------- fused SAGE GEMM: out = relu(Ag@Wl^T + b + Bx@Wr^T) ----------------
// Virtual K=256 ([Ag | Bx] against g_WT). Block: 128x128, 256 threads, 8x8/thread.
// Inner product uses packed fma.rn.f32x2 (FFMA2): 32 dual-FMA instrs per kk
// instead of 64 scalar FFMA -> ~2x fp32 pipe throughput.
__global__ void __launch_bounds__(256, 2)
k_gemm(const float* __restrict__ Ag, const float* __restrict__ Bx,
       const float* __restrict__ WT, const float* __restrict__ bias,
       float* __restrict__ out) {
    __shared__ float sA[16][132];   // [kk][m], padded
    __shared__ __align__(16) float sW[16][128];   // [kk][n]
    int tid = threadIdx.x;
    int tx = tid & 15, ty = tid >> 4;
    int m0 = blockIdx.x * 128;

    int lm = tid >> 1;               // row this thread loads (0..127)
    int lk = (tid & 1) * 8;          // k-offset within tile
    int wkk = tid >> 5;              // 0..7
    int wn = (tid & 31) * 4;

    bool rowok = (m0 + lm) < NN;

    float4 pa0, pa1, pw0, pw1;

    auto LD = [&](int kt) {
        int ks = kt * 16;
        const float* src = (ks < DD) ? Ag : Bx;
        int kb = ks & (DD - 1);
        if (rowok) {
            const float4* p = (const float4*)(src + (size_t)(m0 + lm) * DD + kb + lk);
            pa0 = p[0]; pa1 = p[1];
        } else {
            pa0 = make_float4(0, 0, 0, 0); pa1 = pa0;
        }
        pw0 = *(const float4*)(WT + (ks + wkk) * DD + wn);
        pw1 = *(const float4*)(WT + (ks + wkk + 8) * DD + wn);
    };

    unsigned long long acc[8][4];
    {
        unsigned long long z;
        float zf = 0.f;
        PACK_F32X2(z, zf, zf);
#pragma unroll
        for (int i = 0; i < 8; i++)
#pragma unroll
            for (int j = 0; j < 4; j++) acc[i][j] = z;
    }

    LD(0);
#pragma unroll
    for (int kt = 0; kt < 16; kt++) {
        sA[lk + 0][lm] = pa0.x; sA[lk + 1][lm] = pa0.y;
        sA[lk + 2][lm] = pa0.z; sA[lk + 3][lm] = pa0.w;
        sA[lk + 4][lm] = pa1.x; sA[lk + 5][lm] = pa1.y;
        sA[lk + 6][lm] = pa1.z; sA[lk + 7][lm] = pa1.w;
        *(float4*)&sW[wkk][wn] = pw0;
        *(float4*)&sW[wkk + 8][wn] = pw1;
        __syncthreads();
        if (kt < 15) LD(kt + 1);
#pragma unroll
        for (int kk = 0; kk < 16; kk++) {
            float a[8];
            *(float4*)(a)     = *(float4*)&sA[kk][ty * 8];
            *(float4*)(a + 4) = *(float4*)&sA[kk][ty * 8 + 4];
            ulonglong2 wv0 = *(ulonglong2*)&sW[kk][tx * 8];
            ulonglong2 wv1 = *(ulonglong2*)&sW[kk][tx * 8 + 4];
            unsigned long long wp[4] = {wv0.x, wv0.y, wv1.x, wv1.y};
#pragma unroll
            for (int i = 0; i < 8; i++) {
                unsigned long long aa;
                PACK_F32X2(aa, a[i], a[i]);
#pragma unroll
                for (int p = 0; p < 4; p++)
                    FMA_F32X2(acc[i][p], aa, wp[p], acc[i][p]);
            }
        }
        __syncthreads();
    }

    float b[8];
    *(float4*)(b)     = *(const float4*)(bias + tx * 8);
    *(float4*)(b + 4) = *(const float4*)(bias + tx * 8 + 4);
#pragma unroll
    for (int i = 0; i < 8; i++) {
        int m = m0 + ty * 8 + i;
        if (m < NN) {
            float c[8];
#pragma unroll
            for (int p = 0; p < 4; p++)
                UNPACK_F32X2(c[2 * p], c[2 * p + 1], acc[i][p]);
            float4 o0, o1;
            o0.x = fmaxf(c[0] + b[0], 0.f);
            o0.y = fmaxf(c[1] + b[1], 0.f);
            o0.z = fmaxf(c[2] + b[2], 0.f);
            o0.w = fmaxf(c[3] + b[3], 0.f);
            o1.x = fmaxf(c[4] + b[4], 0.f);
            o1.y = fmaxf(c[5] + b[5], 0.f);
            o1.z = fmaxf(c[6] + b[6], 0.f);
            o1.w = fmaxf(c[7] + b[7], 0.f);
            *(float4*)(out + (size_t)m * DD + tx * 8)     = o0;
            *(float4*)(out + (size_t)m * DD + tx * 8 + 4) = o1;
        }
    }
}

// ---------------- global add pool (batch is sorted, int32) ----------------
#define NPB 256
__global__ void k_pool(const float* __restrict__ h, const int* __restrict__ batch) {
    int t = threadIdx.x;                 // channel 0..127
    int start = blockIdx.x * NPB;
    int end = start + NPB; if (end > NN) end = NN;
    if (start >= NN) return;
    int cur = batch[start];
    float sum = 0.f;
    for (int i = start; i < end; i++) {
        int b = __ldg(&batch[i]);
        if (b != cur) {
            atomicAdd(&g_pool[cur * DD + t], sum);
            sum = 0.f; cur = b;
        }
        sum += h[(size_t)i * DD + t];
    }
    atomicAdd(&g_pool[cur * DD + t], sum);
}

// ---------------- LayerNorm + final linear: one warp per graph ----------------
__global__ void k_final(const float* __restrict__ ln_g, const float* __restrict__ ln_b,
                        const float* __restrict__ Wlin, const float* __restrict__ blin,
                        float* __restrict__ out) {
    int w = (blockIdx.x * blockDim.x + threadIdx.x) >> 5;
    int lane = threadIdx.x & 31;
    if (w >= NG) return;
    float4 v = ((const float4*)g_pool)[w * 32 + lane];
    float s = v.x + v.y + v.z + v.w;
#pragma unroll
    for (int o = 16; o; o >>= 1) s += __shfl_xor_sync(0xffffffffu, s, o);
    float mean = s * (1.0f / 128.0f);
    float dx = v.x - mean, dy = v.y - mean, dz = v.z - mean, dw = v.w - mean;
    float q = dx * dx + dy * dy + dz * dz + dw * dw;
#pragma unroll
    for (int o = 16; o; o >>= 1) q += __shfl_xor_sync(0xffffffffu, q, o);
    float var = q * (1.0f / 128.0f);
    float r = rsqrtf(var + 1e-5f);
    float4 gg = ((const float4*)ln_g)[lane];
    float4 bb = ((const float4*)ln_b)[lane];
    float n0 = dx * r * gg.x + bb.x;
    float n1 = dy * r * gg.y + bb.y;
    float n2 = dz * r * gg.z + bb.z;
    float n3 = dw * r * gg.w + bb.w;
    float4 w0 = ((const float4*)Wlin)[lane];        // row 0
    float4 w1 = ((const float4*)Wlin)[32 + lane];   // row 1
    float d0 = n0 * w0.x + n1 * w0.y + n2 * w0.z + n3 * w0.w;
    float d1 = n0 * w1.x + n1 * w1.y + n2 * w1.z + n3 * w1.w;
#pragma unroll
    for (int o = 16; o; o >>= 1) {
        d0 += __shfl_xor_sync(0xffffffffu, d0, o);
        d1 += __shfl_xor_sync(0xffffffffu, d1, o);
    }
    if (lane == 0) {
        out[w * 2 + 0] = d0 + blin[0];
        out[w * 2 + 1] = d1 + blin[1];
    }
}

// ---------------- launch ----------------
extern "C" void kernel_launch(void* const* d_in, const int* in_sizes, int n_in,
                              void* d_out, int out_size) {
    const float* x     = (const float*)d_in[0];
    const int*   ei    = (const int*)d_in[1];
    const int*   bat   = (const int*)d_in[2];
    const float* W1l   = (const float*)d_in[3];
    const float* b1l   = (const float*)d_in[4];
    const float* W1r   = (const float*)d_in[5];
    const float* W2l   = (const float*)d_in[6];
    const float* b2l   = (const float*)d_in[7];
    const float* W2r   = (const float*)d_in[8];
    const float* ln_g  = (const float*)d_in[9];
    const float* ln_b  = (const float*)d_in[10];
    const float* Wlin  = (const float*)d_in[11];
    const float* blin  = (const float*)d_in[12];

    const int* src = ei;
    const int* dst = ei + NE;

    float *agg, *h1, *h2, *wt1, *wt2;
    cudaGetSymbolAddress((void**)&agg, g_agg);
    cudaGetSymbolAddress((void**)&h1,  g_h1);
    cudaGetSymbolAddress((void**)&h2,  g_h2);
    cudaGetSymbolAddress((void**)&wt1, g_WT1);
    cudaGetSymbolAddress((void**)&wt2, g_WT2);

    k_init<<<NB_INIT, 256>>>();
    k_transp<<<128, 256>>>(W1l, W1r, W2l, W2r);
    k_deg<<<(NE + 255) / 256, 256>>>(dst);
    k_scanA<<<NB_SCAN, 256>>>();
    k_scanB<<<1, 512>>>();
    k_scanC<<<NB_SCAN + 1, 256>>>();
    k_scatter<<<(NE + 255) / 256, 256>>>(src, dst);

    // layer 1
    k_agg<<<(NN * 32 + 255) / 256, 256>>>(x, agg);
    k_gemm<<<(NN + 127) / 128, 256>>>(agg, x, wt1, b1l, h1);
    // layer 2
    k_agg<<<(NN * 32 + 255) / 256, 256>>>(h1, agg);
    k_gemm<<<(NN + 127) / 128, 256>>>(agg, h1, wt2, b2l, h2);

    // pool + layernorm + linear
    k_pool<<<(NN + NPB - 1) / NPB, 128>>>(h2, bat);
    k_final<<<(NG * 32 + 255) / 256, 256>>>(ln_g, ln_b, Wlin, blin, (float*)d_out);
}

// round 5
// speedup vs baseline: 1.5116x; 1.3596x over previous
#include <cuda_runtime.h>
#include <cuda_bf16.h>
#include <cstdint>

#define NN 100000
#define NE 1600000
#define NG 1024
#define DD 128
#define NB_SCAN 391   // ceil(NN/256)
#define NB_INIT 512   // ceil(max(NN, NG*DD)/256)

// ---------------- scratch (device globals; no allocation allowed) ----------------
__device__ float g_agg[NN * DD];
__device__ float g_h1[NN * DD];
__device__ float g_h2[NN * DD];
__device__ float g_pool[NG * DD];
// W in fragment order: [layer][j(n-tile 0..15)][s(k-step 0..15)][lane 0..31] -> uint2 (b0,b1)
__device__ uint2 g_WfH[2 * 16 * 16 * 32];
__device__ uint2 g_WfL[2 * 16 * 16 * 32];
__device__ int   g_deg[NN];
__device__ int   g_rowptr[NN + 1];
__device__ int   g_cursor[NN];
__device__ int   g_esrc[NE];
__device__ int   g_bsum[512];
__device__ int   g_boff[512];

// ---------------- helpers ----------------
__device__ __forceinline__ uint32_t smem_to_u32(const void* p) {
    uint32_t a;
    asm("{ .reg .u64 t; cvta.to.shared.u64 t, %1; cvt.u32.u64 %0, t; }" : "=r"(a) : "l"(p));
    return a;
}
__device__ __forceinline__ uint32_t bf2u(__nv_bfloat162 v) { return *reinterpret_cast<uint32_t*>(&v); }

#define LDM_X4(r, addr) \
    asm volatile("ldmatrix.sync.aligned.m8n8.x4.shared.b16 {%0,%1,%2,%3}, [%4];" \
        : "=r"((r)[0]), "=r"((r)[1]), "=r"((r)[2]), "=r"((r)[3]) : "r"(addr))

#define MMA_BF16(c, a, b) \
    asm volatile("mma.sync.aligned.m16n8k16.row.col.f32.bf16.bf16.f32 " \
        "{%0,%1,%2,%3}, {%4,%5,%6,%7}, {%8,%9}, {%0,%1,%2,%3};" \
        : "+f"((c)[0]), "+f"((c)[1]), "+f"((c)[2]), "+f"((c)[3]) \
        : "r"((a)[0]), "r"((a)[1]), "r"((a)[2]), "r"((a)[3]), "r"((b).x), "r"((b).y))

// ---------------- init ----------------
__global__ void k_init() {
    int i = blockIdx.x * blockDim.x + threadIdx.x;
    if (i < NN) { g_deg[i] = 0; g_cursor[i] = 0; }
    if (i < NG * DD) g_pool[i] = 0.0f;
}

// split weights into bf16 hi/lo fragments, mma.m16n8k16 B-operand order
__global__ void k_wfrag(const float* __restrict__ W1l, const float* __restrict__ W1r,
                        const float* __restrict__ W2l, const float* __restrict__ W2r) {
    int i = blockIdx.x * blockDim.x + threadIdx.x;   // 0 .. 16383
    if (i >= 2 * 16 * 16 * 32) return;
    int lane = i & 31;
    int s = (i >> 5) & 15;
    int j = (i >> 9) & 15;
    int layer = i >> 13;
    int n = j * 8 + (lane >> 2);
    int k = s * 16 + (lane & 3) * 2;
    const float* Wl = layer ? W2l : W1l;
    const float* Wr = layer ? W2r : W1r;
    float w[4];
#pragma unroll
    for (int q = 0; q < 4; q++) {
        int kk = k + (q >> 1) * 8 + (q & 1);
        w[q] = (kk < DD) ? Wl[n * DD + kk] : Wr[n * DD + (kk - DD)];
    }
    __nv_bfloat16 h[4], l[4];
#pragma unroll
    for (int q = 0; q < 4; q++) {
        h[q] = __float2bfloat16(w[q]);
        l[q] = __float2bfloat16(w[q] - __bfloat162float(h[q]));
    }
    __nv_bfloat162 h01; h01.x = h[0]; h01.y = h[1];
    __nv_bfloat162 h23; h23.x = h[2]; h23.y = h[3];
    __nv_bfloat162 l01; l01.x = l[0]; l01.y = l[1];
    __nv_bfloat162 l23; l23.x = l[2]; l23.y = l[3];
    g_WfH[i] = make_uint2(bf2u(h01), bf2u(h23));
    g_WfL[i] = make_uint2(bf2u(l01), bf2u(l23));
}

// ---------------- CSR build (edge_index is int32: JAX x64 disabled) ----------------
__global__ void k_deg(const int* __restrict__ dst) {
    int i = blockIdx.x * blockDim.x + threadIdx.x;
    if (i < NE) atomicAdd(&g_deg[dst[i]], 1);
}

__global__ void k_scanA() {
    __shared__ int s[256];
    int b = blockIdx.x, t = threadIdx.x;
    int i = b * 256 + t;
    int v = (i < NN) ? g_deg[i] : 0;
    s[t] = v;
    __syncthreads();
#pragma unroll
    for (int off = 1; off < 256; off <<= 1) {
        int add = (t >= off) ? s[t - off] : 0;
        __syncthreads();
        s[t] += add;
        __syncthreads();
    }
    if (i < NN) g_rowptr[i] = s[t] - v;
    if (t == 255) g_bsum[b] = s[255];
}

__global__ void k_scanB() {
    __shared__ int s[512];
    int t = threadIdx.x;
    int v = (t < NB_SCAN) ? g_bsum[t] : 0;
    s[t] = v;
    __syncthreads();
#pragma unroll
    for (int off = 1; off < 512; off <<= 1) {
        int add = (t >= off) ? s[t - off] : 0;
        __syncthreads();
        s[t] += add;
        __syncthreads();
    }
    if (t < NB_SCAN) g_boff[t] = s[t] - v;
}

__global__ void k_scanC() {
    int i = blockIdx.x * blockDim.x + threadIdx.x;
    if (i < NN) g_rowptr[i] += g_boff[i >> 8];
    if (i == 0) g_rowptr[NN] = NE;
}

__global__ void k_scatter(const int* __restrict__ src, const int* __restrict__ dst) {
    int i = blockIdx.x * blockDim.x + threadIdx.x;
    if (i >= NE) return;
    int d = dst[i];
    int pos = atomicAdd(&g_cursor[d], 1);
    g_esrc[g_rowptr[d] + pos] = src[i];
}

// ---------------- mean aggregation: warp per destination node ----------------
__global__ void k_agg(const float* __restrict__ in, float* __restrict__ out) {
    int w = (blockIdx.x * blockDim.x + threadIdx.x) >> 5;
    int lane = threadIdx.x & 31;
    if (w >= NN) return;
    int beg = g_rowptr[w], end = g_rowptr[w + 1];
    const float4* in4 = (const float4*)in;
    float ax = 0.f, ay = 0.f, az = 0.f, aw = 0.f;
#pragma unroll 4
    for (int e = beg; e < end; e++) {
        int s = __ldg(&g_esrc[e]);
        float4 v = __ldg(&in4[s * 32 + lane]);
        ax += v.x; ay += v.y; az += v.z; aw += v.w;
    }
    float inv = (end > beg) ? 1.0f / (float)(end - beg) : 0.0f;
    float4 r; r.x = ax * inv; r.y = ay * inv; r.z = az * inv; r.w = aw * inv;
    ((float4*)out)[w * 32 + lane] = r;
}

// ---------------- mma.sync SAGE GEMM ----------------
// out = relu([Ag|Bx] @ W^T + bias), M-tile 128, N=128, K=256 (4 smem chunks of 64).
// 3-term bf16 split: D = Ah*Wh + Al*Wh + Ah*Wl (fp32 accum on tensor pipe).
#define SA_STRIDE 72   // bf16 elems per row (144B), conflict-free ldmatrix
__global__ void __launch_bounds__(256, 2)
k_gemm_mma(const float* __restrict__ Ag, const float* __restrict__ Bx,
           const uint2* __restrict__ WfH, const uint2* __restrict__ WfL,
           const float* __restrict__ bias, float* __restrict__ out) {
    __shared__ __nv_bfloat16 sAh[128 * SA_STRIDE];
    __shared__ __nv_bfloat16 sAl[128 * SA_STRIDE];
    int tid = threadIdx.x;
    int wid = tid >> 5, lane = tid & 31;
    int m0 = blockIdx.x * 128;
    int wm = wid & 3, wn = wid >> 2;   // warp tile: rows wm*32, cols wn*64

    float acc[2][8][4];
#pragma unroll
    for (int a = 0; a < 2; a++)
#pragma unroll
        for (int b = 0; b < 8; b++)
#pragma unroll
            for (int q = 0; q < 4; q++) acc[a][b][q] = 0.f;

    // fill coords: each thread loads one row-half (32 f32) per chunk
    int frow = tid >> 1, fhalf = tid & 1;
    bool okrow = (m0 + frow) < NN;

    // ldmatrix lane addressing: group g (0..3), row-in-group ri
    int g = lane >> 3, ri = lane & 7;
    uint32_t sAh_u = smem_to_u32(sAh);
    uint32_t sAl_u = smem_to_u32(sAl);

#pragma unroll 1
    for (int c = 0; c < 4; c++) {
        // ---- fill A chunk (64 cols) as bf16 hi/lo ----
        const float* srcm = (c < 2) ? Ag : Bx;
        int kcol = (c & 1) * 64;
        const float4* sp = (const float4*)(srcm + (size_t)(m0 + frow) * DD + kcol + fhalf * 32);
        uint32_t dst_off = (uint32_t)frow * SA_STRIDE + (uint32_t)fhalf * 32;
#pragma unroll
        for (int q = 0; q < 8; q++) {
            float4 f;
            if (okrow) f = sp[q];
            else f = make_float4(0.f, 0.f, 0.f, 0.f);
            __nv_bfloat162 h01 = __floats2bfloat162_rn(f.x, f.y);
            __nv_bfloat162 h23 = __floats2bfloat162_rn(f.z, f.w);
            __nv_bfloat162 l01 = __floats2bfloat162_rn(f.x - __bfloat162float(h01.x),
                                                       f.y - __bfloat162float(h01.y));
            __nv_bfloat162 l23 = __floats2bfloat162_rn(f.z - __bfloat162float(h23.x),
                                                       f.w - __bfloat162float(h23.y));
            *(uint2*)(sAh + dst_off + q * 4) = make_uint2(bf2u(h01), bf2u(h23));
            *(uint2*)(sAl + dst_off + q * 4) = make_uint2(bf2u(l01), bf2u(l23));
        }
        __syncthreads();

        // ---- compute 4 k-steps of this chunk ----
#pragma unroll
        for (int ss = 0; ss < 4; ss++) {
            int s = c * 4 + ss;      // global k-step (for W frags)
            int k0 = ss * 16;        // within chunk
            uint32_t Ah[2][4], Al[2][4];
#pragma unroll
            for (int mt = 0; mt < 2; mt++) {
                uint32_t row = (uint32_t)(wm * 32 + mt * 16 + (g & 1) * 8 + ri);
                uint32_t byo = (row * SA_STRIDE + (uint32_t)(k0 + (g >> 1) * 8)) * 2;
                LDM_X4(Ah[mt], sAh_u + byo);
                LDM_X4(Al[mt], sAl_u + byo);
            }
#pragma unroll
            for (int nt = 0; nt < 8; nt++) {
                int idx = (((wn * 8 + nt) * 16 + s) << 5) + lane;
                uint2 bh = __ldg(&WfH[idx]);
                uint2 bl = __ldg(&WfL[idx]);
                MMA_BF16(acc[0][nt], Ah[0], bh);
                MMA_BF16(acc[1][nt], Ah[1], bh);
                MMA_BF16(acc[0][nt], Al[0], bh);
                MMA_BF16(acc[1][nt], Al[1], bh);
                MMA_BF16(acc[0][nt], Ah[0], bl);
                MMA_BF16(acc[1][nt], Ah[1], bl);
            }
        }
        __syncthreads();
    }

    // ---- epilogue: bias + relu + store ----
    int r_in = lane >> 2;
    int n_in = (lane & 3) * 2;
#pragma unroll
    for (int nt = 0; nt < 8; nt++) {
        int n = wn * 64 + nt * 8 + n_in;
        float2 bb = *(const float2*)(bias + n);
#pragma unroll
        for (int mt = 0; mt < 2; mt++) {
            int r0 = m0 + wm * 32 + mt * 16 + r_in;
            if (r0 < NN) {
                float2 o;
                o.x = fmaxf(acc[mt][nt][0] + bb.x, 0.f);
                o.y = fmaxf(acc[mt][nt][1] + bb.y, 0.f);
                *(float2*)(out + (size_t)r0 * DD + n) = o;
            }
            int r1 = r0 + 8;
            if (r1 < NN) {
                float2 o;
                o.x = fmaxf(acc[mt][nt][2] + bb.x, 0.f);
                o.y = fmaxf(acc[mt][nt][3] + bb.y, 0.f);
                *(float2*)(out + (size_t)r1 * DD + n) = o;
            }
        }
    }
}

// ---------------- global add pool (batch is sorted, int32) ----------------
#define NPB 256
__global__ void k_pool(const float* __restrict__ h, const int* __restrict__ batch) {
    int t = threadIdx.x;
    int start = blockIdx.x * NPB;
    int end = start + NPB; if (end > NN) end = NN;
    if (start >= NN) return;
    int cur = batch[start];
    float sum = 0.f;
    for (int i = start; i < end; i++) {
        int b = __ldg(&batch[i]);
        if (b != cur) {
            atomicAdd(&g_pool[cur * DD + t], sum);
            sum = 0.f; cur = b;
        }
        sum += h[(size_t)i * DD + t];
    }
    atomicAdd(&g_pool[cur * DD + t], sum);
}

// ---------------- LayerNorm + final linear: one warp per graph ----------------
__global__ void k_final(const float* __restrict__ ln_g, const float* __restrict__ ln_b,
                        const float* __restrict__ Wlin, const float* __restrict__ blin,
                        float* __restrict__ out) {
    int w = (blockIdx.x * blockDim.x + threadIdx.x) >> 5;
    int lane = threadIdx.x & 31;
    if (w >= NG) return;
    float4 v = ((const float4*)g_pool)[w * 32 + lane];
    float s = v.x + v.y + v.z + v.w;
#pragma unroll
    for (int o = 16; o; o >>= 1) s += __shfl_xor_sync(0xffffffffu, s, o);
    float mean = s * (1.0f / 128.0f);
    float dx = v.x - mean, dy = v.y - mean, dz = v.z - mean, dw = v.w - mean;
    float q = dx * dx + dy * dy + dz * dz + dw * dw;
#pragma unroll
    for (int o = 16; o; o >>= 1) q += __shfl_xor_sync(0xffffffffu, q, o);
    float var = q * (1.0f / 128.0f);
    float r = rsqrtf(var + 1e-5f);
    float4 gg = ((const float4*)ln_g)[lane];
    float4 bb = ((const float4*)ln_b)[lane];
    float n0 = dx * r * gg.x + bb.x;
    float n1 = dy * r * gg.y + bb.y;
    float n2 = dz * r * gg.z + bb.z;
    float n3 = dw * r * gg.w + bb.w;
    float4 w0 = ((const float4*)Wlin)[lane];
    float4 w1 = ((const float4*)Wlin)[32 + lane];
    float d0 = n0 * w0.x + n1 * w0.y + n2 * w0.z + n3 * w0.w;
    float d1 = n0 * w1.x + n1 * w1.y + n2 * w1.z + n3 * w1.w;
#pragma unroll
    for (int o = 16; o; o >>= 1) {
        d0 += __shfl_xor_sync(0xffffffffu, d0, o);
        d1 += __shfl_xor_sync(0xffffffffu, d1, o);
    }
    if (lane == 0) {
        out[w * 2 + 0] = d0 + blin[0];
        out[w * 2 + 1] = d1 + blin[1];
    }
}

// ---------------- launch ----------------
extern "C" void kernel_launch(void* const* d_in, const int* in_sizes, int n_in,
                              void* d_out, int out_size) {
    const float* x     = (const float*)d_in[0];
    const int*   ei    = (const int*)d_in[1];
    const int*   bat   = (const int*)d_in[2];
    const float* W1l   = (const float*)d_in[3];
    const float* b1l   = (const float*)d_in[4];
    const float* W1r   = (const float*)d_in[5];
    const float* W2l   = (const float*)d_in[6];
    const float* b2l   = (const float*)d_in[7];
    const float* W2r   = (const float*)d_in[8];
    const float* ln_g  = (const float*)d_in[9];
    const float* ln_b  = (const float*)d_in[10];
    const float* Wlin  = (const float*)d_in[11];
    const float* blin  = (const float*)d_in[12];

    const int* src = ei;
    const int* dst = ei + NE;

    float *agg, *h1, *h2;
    uint2 *wfh, *wfl;
    cudaGetSymbolAddress((void**)&agg, g_agg);
    cudaGetSymbolAddress((void**)&h1,  g_h1);
    cudaGetSymbolAddress((void**)&h2,  g_h2);
    cudaGetSymbolAddress((void**)&wfh, g_WfH);
    cudaGetSymbolAddress((void**)&wfl, g_WfL);

    k_init<<<NB_INIT, 256>>>();
    k_wfrag<<<64, 256>>>(W1l, W1r, W2l, W2r);
    k_deg<<<(NE + 255) / 256, 256>>>(dst);
    k_scanA<<<NB_SCAN, 256>>>();
    k_scanB<<<1, 512>>>();
    k_scanC<<<NB_SCAN + 1, 256>>>();
    k_scatter<<<(NE + 255) / 256, 256>>>(src, dst);

    int nblk = (NN + 127) / 128;
    const int LSTRIDE = 16 * 16 * 32;   // per-layer frag stride
    // layer 1
    k_agg<<<(NN * 32 + 255) / 256, 256>>>(x, agg);
    k_gemm_mma<<<nblk, 256>>>(agg, x, wfh, wfl, b1l, h1);
    // layer 2
    k_agg<<<(NN * 32 + 255) / 256, 256>>>(h1, agg);
    k_gemm_mma<<<nblk, 256>>>(agg, h1, wfh + LSTRIDE, wfl + LSTRIDE, b2l, h2);

    // pool + layernorm + linear
    k_pool<<<(NN + NPB - 1) / NPB, 128>>>(h2, bat);
    k_final<<<(NG * 32 + 255) / 256, 256>>>(ln_g, ln_b, Wlin, blin, (float*)d_out);
}